// round 1
// baseline (speedup 1.0000x reference)
#include <cuda_runtime.h>
#include <cuda_bf16.h>
#include <cstdint>

#define Cc 128
#define Gg 2000
#define Hh 256
#define CEe 64
#define GEe 64

// ---------------- scratch (device globals; no allocation) ----------------
__device__ float d_ce_g[Cc * CEe];            // [128,64]
__device__ float d_A_g[Cc * Hh];              // [128,256]
__device__ float d_B_g[Gg * Hh];              // [2000,256]
__device__ float d_q_g[Gg * Hh];              // [2000,256]
__device__ float d_cg_g[Gg];                  // [2000]
__device__ float d_x2_g[(size_t)Cc * Gg * Hh];// [g][c][h] = 262 MB

__device__ __forceinline__ float eluf(float x) {
    return x > 0.f ? x : (__expf(x) - 1.f);
}

__device__ __forceinline__ unsigned long long pack2(float x, float y) {
    unsigned long long r;
    asm("mov.b64 %0, {%1,%2};" : "=l"(r) : "f"(x), "f"(y));
    return r;
}
__device__ __forceinline__ void unpack2(unsigned long long v, float& x, float& y) {
    asm("mov.b64 {%0,%1}, %2;" : "=f"(x), "=f"(y) : "l"(v));
}
__device__ __forceinline__ unsigned long long ffma2(unsigned long long a, unsigned long long b, unsigned long long c) {
    unsigned long long d;
    asm("fma.rn.f32x2 %0, %1, %2, %3;" : "=l"(d) : "l"(a), "l"(b), "l"(c));
    return d;
}

// ---------------- k_ce: ce = elu(ctrl@ce_w1+b1)@ce_w2+b2  [128,64] ------
__global__ __launch_bounds__(1024) void k_ce(
    const float* __restrict__ ctrl, const float* __restrict__ ce_w1,
    const float* __restrict__ ce_b1, const float* __restrict__ ce_w2,
    const float* __restrict__ ce_b2)
{
    int c = blockIdx.x, tid = threadIdx.x;
    __shared__ float row[Gg];
    __shared__ float part[4][256];
    __shared__ float h1[256];
    for (int i = tid; i < Gg; i += 1024) row[i] = ctrl[c * Gg + i];
    __syncthreads();
    int sl = tid >> 8, t = tid & 255;
    float acc = 0.f;
    for (int k = sl * 500; k < sl * 500 + 500; k++)
        acc += row[k] * ce_w1[k * 256 + t];
    part[sl][t] = acc;
    __syncthreads();
    if (tid < 256) {
        float v = part[0][tid] + part[1][tid] + part[2][tid] + part[3][tid] + ce_b1[tid];
        h1[tid] = eluf(v);
    }
    __syncthreads();
    if (tid < 256) {
        int s2 = tid >> 6, e = tid & 63;
        float a2 = 0.f;
        for (int h = s2 * 64; h < s2 * 64 + 64; h++)
            a2 += h1[h] * ce_w2[h * 64 + e];
        part[s2][e] = a2;
    }
    __syncthreads();
    if (tid < 64)
        d_ce_g[c * 64 + tid] = part[0][tid] + part[1][tid] + part[2][tid] + part[3][tid] + ce_b2[tid];
}

// ---------------- k_A: A[c,h] = ce[c,:] . w1[1:65,h] --------------------
__global__ void k_A(const float* __restrict__ g_w1)
{
    int c = blockIdx.x, tid = threadIdx.x;
    __shared__ float ces[64];
    if (tid < 64) ces[tid] = d_ce_g[c * 64 + tid];
    __syncthreads();
    float a = 0.f;
#pragma unroll 8
    for (int e = 0; e < 64; e++)
        a += ces[e] * g_w1[(1 + e) * 256 + tid];
    d_A_g[c * 256 + tid] = a;
}

// ------ k_B: B[g,h] = ge.w1[65:129] + shift*w1[129] + 128*w1[130] + b1 --
__global__ void k_B(const int* __restrict__ gidx, const float* __restrict__ shift_vec,
                    const float* __restrict__ gene_table, const float* __restrict__ g_w1,
                    const float* __restrict__ g_b1)
{
    int g = blockIdx.x, tid = threadIdx.x;
    __shared__ float ges[64];
    __shared__ float shs;
    int gs = gidx[g];
    if (tid < 64) ges[tid] = gene_table[gs * 64 + tid];
    if (tid == 0) shs = shift_vec[gs];
    __syncthreads();
    float a = g_b1[tid] + 128.0f * g_w1[130 * 256 + tid] + shs * g_w1[129 * 256 + tid];
#pragma unroll 8
    for (int e = 0; e < 64; e++)
        a += ges[e] * g_w1[(65 + e) * 256 + tid];
    d_B_g[g * 256 + tid] = a;
}

// -- k_pq: p[g,h]=mean_c elu(ctrl*r + A + B); q[g,:] = p@W2b + b2 (8 g/blk)
__global__ __launch_bounds__(256) void k_pq(
    const float* __restrict__ ctrl, const int* __restrict__ gidx,
    const float* __restrict__ g_w1, const float* __restrict__ g_w2,
    const float* __restrict__ g_b2)
{
    __shared__ float ctrl_s[8][128];
    __shared__ float Bs[8][256];
    __shared__ float ps[8][256];
    __shared__ int gss[8];
    int tid = threadIdx.x, g0 = blockIdx.x * 8;
    if (tid < 8) gss[tid] = gidx[g0 + tid];
    __syncthreads();
    for (int i = tid; i < 1024; i += 256) {
        int c = i >> 3, gi = i & 7;
        ctrl_s[gi][c] = ctrl[c * Gg + gss[gi]];
    }
    for (int gi = 0; gi < 8; gi++) Bs[gi][tid] = d_B_g[(g0 + gi) * 256 + tid];
    __syncthreads();
    float rv = g_w1[tid];  // w1 row 0 (ctrl coefficient)
    for (int gi = 0; gi < 8; gi++) {
        float Bv = Bs[gi][tid];
        float s = 0.f;
#pragma unroll 4
        for (int c = 0; c < 128; c++) {
            float v = ctrl_s[gi][c] * rv + d_A_g[c * 256 + tid] + Bv;
            s += eluf(v);
        }
        ps[gi][tid] = s * (1.f / 128.f);
    }
    __syncthreads();
    float qv[8];
#pragma unroll
    for (int gi = 0; gi < 8; gi++) qv[gi] = g_b2[tid];
    for (int hh = 0; hh < 256; hh++) {
        float wv = g_w2[(256 + hh) * 256 + tid];
#pragma unroll
        for (int gi = 0; gi < 8; gi++) qv[gi] += ps[gi][hh] * wv;
    }
    for (int gi = 0; gi < 8; gi++) d_q_g[(g0 + gi) * 256 + tid] = qv[gi];
}

// ---- k3: per-gene GEMM [128x256]@[256x256] + q; writes x2; p2 -> cgene --
// smem layout (floats): ctrl_s[128] | rs[256] | Bs[256] | qs[256] | xs[64*132] | ws[16384]
#define K3_SMEM_FLOATS (128 + 256 + 256 + 256 + 64 * 132 + 16384)
__global__ __launch_bounds__(512, 1) void k3(
    const float* __restrict__ ctrl, const int* __restrict__ gidx,
    const float* __restrict__ g_w1, const float* __restrict__ g_w2,
    const float* __restrict__ g_w3, const float* __restrict__ g_b3)
{
    extern __shared__ float sm[];
    float* ctrl_s = sm;
    float* rs = sm + 128;
    float* Bs = sm + 384;
    float* qs = sm + 640;
    float* xs = sm + 896;        // [64][132]
    float* ws = sm + 9344;       // [64][256]

    int g = blockIdx.x, tid = threadIdx.x;
    int gs = gidx[g];
    for (int i = tid; i < 128; i += 512) ctrl_s[i] = ctrl[i * Gg + gs];
    for (int i = tid; i < 256; i += 512) {
        rs[i] = g_w1[i];
        Bs[i] = d_B_g[g * 256 + i];
        qs[i] = d_q_g[g * 256 + i];
    }

    unsigned long long acc[8][4];
#pragma unroll
    for (int i = 0; i < 8; i++)
#pragma unroll
        for (int j = 0; j < 4; j++) acc[i][j] = 0ull;

    int lane = tid & 31, rg = tid >> 5;
    int row0 = rg * 8, col0 = lane * 8;

    for (int kc = 0; kc < 4; kc++) {
        __syncthreads();
        const float* wsrc = g_w2 + kc * 16384;  // W2a rows [kc*64, kc*64+64)
        for (int i = tid; i < 16384; i += 512) ws[i] = wsrc[i];
        for (int i = tid; i < 8192; i += 512) {
            int c = i >> 6, hl = i & 63, h = kc * 64 + hl;
            float v = ctrl_s[c] * rs[h] + d_A_g[c * 256 + h] + Bs[h];
            xs[hl * 132 + c] = eluf(v);
        }
        __syncthreads();
#pragma unroll 2
        for (int kk = 0; kk < 64; kk++) {
            float4 a0 = *(const float4*)(xs + kk * 132 + row0);
            float4 a1 = *(const float4*)(xs + kk * 132 + row0 + 4);
            float4 b0 = *(const float4*)(ws + kk * 256 + col0);
            float4 b1 = *(const float4*)(ws + kk * 256 + col0 + 4);
            unsigned long long bp[4];
            bp[0] = pack2(b0.x, b0.y); bp[1] = pack2(b0.z, b0.w);
            bp[2] = pack2(b1.x, b1.y); bp[3] = pack2(b1.z, b1.w);
            float a[8] = {a0.x, a0.y, a0.z, a0.w, a1.x, a1.y, a1.z, a1.w};
#pragma unroll
            for (int i = 0; i < 8; i++) {
                unsigned long long ap = pack2(a[i], a[i]);
#pragma unroll
                for (int j = 0; j < 4; j++) acc[i][j] = ffma2(ap, bp[j], acc[i][j]);
            }
        }
    }
    __syncthreads();

    // epilogue: add q, write x2[g][c][h], collect column sums for p2
    float cs[8];
#pragma unroll
    for (int j = 0; j < 8; j++) cs[j] = 0.f;
    size_t base = ((size_t)g * 128 + row0) * 256 + col0;
#pragma unroll
    for (int i = 0; i < 8; i++) {
        float v[8];
#pragma unroll
        for (int j = 0; j < 4; j++) unpack2(acc[i][j], v[2 * j], v[2 * j + 1]);
#pragma unroll
        for (int jj = 0; jj < 8; jj++) {
            v[jj] += qs[col0 + jj];
            cs[jj] += v[jj];
        }
        float4 o0 = make_float4(v[0], v[1], v[2], v[3]);
        float4 o1 = make_float4(v[4], v[5], v[6], v[7]);
        *(float4*)(d_x2_g + base + (size_t)i * 256) = o0;
        *(float4*)(d_x2_g + base + (size_t)i * 256 + 4) = o1;
    }

    // p2[g,h] = mean_c x2; cgene[g] = sum_h w3b[h]*elu(p2[h]) + b3
    float* red = ws;  // [16][256], safe after sync above
    *(float4*)(red + rg * 256 + col0) = make_float4(cs[0], cs[1], cs[2], cs[3]);
    *(float4*)(red + rg * 256 + col0 + 4) = make_float4(cs[4], cs[5], cs[6], cs[7]);
    __syncthreads();
    float* rbuf = xs;  // reuse
    if (tid < 256) {
        float s = 0.f;
#pragma unroll
        for (int r = 0; r < 16; r++) s += red[r * 256 + tid];
        float p2 = s * (1.f / 128.f);
        rbuf[tid] = g_w3[256 + tid] * eluf(p2);
    }
    __syncthreads();
    for (int off = 128; off > 0; off >>= 1) {
        if (tid < off) rbuf[tid] += rbuf[tid + off];
        __syncthreads();
    }
    if (tid == 0) d_cg_g[g] = rbuf[0] + g_b3[0];
}

// ---- k4: x3[c] = sum_h w3a[h]*elu(x2) + cgene; softmax over cells -------
__global__ __launch_bounds__(256) void k4(const float* __restrict__ g_w3,
                                          float* __restrict__ out)
{
    int g = blockIdx.x, tid = threadIdx.x, l = tid & 31, w = tid >> 5;
    __shared__ float w3s[256];
    __shared__ float x3s[128];
    __shared__ float rbuf[128];
    w3s[tid] = g_w3[tid];
    float cgv = d_cg_g[g];
    __syncthreads();
    for (int ci = 0; ci < 16; ci++) {
        int c = w * 16 + ci;
        const float* xr = d_x2_g + ((size_t)g * 128 + c) * 256;
        float s = 0.f;
#pragma unroll
        for (int j = 0; j < 8; j++) {
            int h = l + 32 * j;
            s += w3s[h] * eluf(xr[h]);
        }
#pragma unroll
        for (int o = 16; o > 0; o >>= 1) s += __shfl_xor_sync(0xffffffffu, s, o);
        if (l == 0) x3s[c] = s + cgv;
    }
    __syncthreads();
    if (tid < 128) rbuf[tid] = x3s[tid];
    __syncthreads();
    for (int off = 64; off > 0; off >>= 1) {
        if (tid < off) rbuf[tid] = fmaxf(rbuf[tid], rbuf[tid + off]);
        __syncthreads();
    }
    float m = rbuf[0];
    __syncthreads();
    float e = 0.f;
    if (tid < 128) { e = __expf(x3s[tid] - m); rbuf[tid] = e; }
    __syncthreads();
    for (int off = 64; off > 0; off >>= 1) {
        if (tid < off) rbuf[tid] += rbuf[tid + off];
        __syncthreads();
    }
    float inv = 1.f / rbuf[0];
    if (tid < 128) out[tid * Gg + g] = e * inv;
}

// -------------------------------------------------------------------------
extern "C" void kernel_launch(void* const* d_in, const int* in_sizes, int n_in,
                              void* d_out, int out_size)
{
    const float* ctrl       = (const float*)d_in[0];
    const float* shift_vec  = (const float*)d_in[1];
    const int*   gidx       = (const int*)d_in[2];
    const float* ce_w1      = (const float*)d_in[3];
    const float* ce_b1      = (const float*)d_in[4];
    const float* ce_w2      = (const float*)d_in[5];
    const float* ce_b2      = (const float*)d_in[6];
    const float* gene_table = (const float*)d_in[7];
    const float* g_w1       = (const float*)d_in[8];
    const float* g_b1       = (const float*)d_in[9];
    const float* g_w2       = (const float*)d_in[10];
    const float* g_b2       = (const float*)d_in[11];
    const float* g_w3       = (const float*)d_in[12];
    const float* g_b3       = (const float*)d_in[13];
    float* out = (float*)d_out;

    cudaFuncSetAttribute(k3, cudaFuncAttributeMaxDynamicSharedMemorySize,
                         K3_SMEM_FLOATS * (int)sizeof(float));

    k_ce<<<Cc, 1024>>>(ctrl, ce_w1, ce_b1, ce_w2, ce_b2);
    k_A<<<Cc, 256>>>(g_w1);
    k_B<<<Gg, 256>>>(gidx, shift_vec, gene_table, g_w1, g_b1);
    k_pq<<<Gg / 8, 256>>>(ctrl, gidx, g_w1, g_w2, g_b2);
    k3<<<Gg, 512, K3_SMEM_FLOATS * sizeof(float)>>>(ctrl, gidx, g_w1, g_w2, g_w3, g_b3);
    k4<<<Gg, 256>>>(g_w3, out);
}

// round 2
// speedup vs baseline: 3.1697x; 3.1697x over previous
#include <cuda_runtime.h>
#include <cuda_bf16.h>
#include <cstdint>

#define Cc 128
#define Gg 2000
#define Hh 256

// ---------------- scratch (device globals; no allocation) ----------------
__device__ float d_ce_g[Cc * 64];             // [128,64]
__device__ float d_A_g[Cc * Hh];              // [128,256]
__device__ float d_B_g[Gg * Hh];              // [2000,256]

__device__ __forceinline__ float eluf(float x) {
    return x > 0.f ? x : (__expf(x) - 1.f);
}

__device__ __forceinline__ unsigned f2tf32(float x) {
    unsigned r;
    asm("cvt.rna.tf32.f32 %0, %1;" : "=r"(r) : "f"(x));
    return r;
}

__device__ __forceinline__ void mma_tf32(float* acc, const unsigned* a, const unsigned* b) {
    asm volatile(
        "mma.sync.aligned.m16n8k8.row.col.f32.tf32.tf32.f32 "
        "{%0,%1,%2,%3}, {%4,%5,%6,%7}, {%8,%9}, {%0,%1,%2,%3};"
        : "+f"(acc[0]), "+f"(acc[1]), "+f"(acc[2]), "+f"(acc[3])
        : "r"(a[0]), "r"(a[1]), "r"(a[2]), "r"(a[3]), "r"(b[0]), "r"(b[1]));
}

// ---------------- k_ce: ce = elu(ctrl@ce_w1+b1)@ce_w2+b2  [128,64] ------
__global__ __launch_bounds__(1024) void k_ce(
    const float* __restrict__ ctrl, const float* __restrict__ ce_w1,
    const float* __restrict__ ce_b1, const float* __restrict__ ce_w2,
    const float* __restrict__ ce_b2)
{
    int c = blockIdx.x, tid = threadIdx.x;
    __shared__ float row[Gg];
    __shared__ float part[4][256];
    __shared__ float h1[256];
    for (int i = tid; i < Gg; i += 1024) row[i] = ctrl[c * Gg + i];
    __syncthreads();
    int sl = tid >> 8, t = tid & 255;
    float acc = 0.f;
    for (int k = sl * 500; k < sl * 500 + 500; k++)
        acc += row[k] * ce_w1[k * 256 + t];
    part[sl][t] = acc;
    __syncthreads();
    if (tid < 256) {
        float v = part[0][tid] + part[1][tid] + part[2][tid] + part[3][tid] + ce_b1[tid];
        h1[tid] = eluf(v);
    }
    __syncthreads();
    if (tid < 256) {
        int s2 = tid >> 6, e = tid & 63;
        float a2 = 0.f;
        for (int h = s2 * 64; h < s2 * 64 + 64; h++)
            a2 += h1[h] * ce_w2[h * 64 + e];
        part[s2][e] = a2;
    }
    __syncthreads();
    if (tid < 64)
        d_ce_g[c * 64 + tid] = part[0][tid] + part[1][tid] + part[2][tid] + part[3][tid] + ce_b2[tid];
}

// ---------------- k_A: A[c,h] = ce[c,:] . w1[1:65,h] --------------------
__global__ void k_A(const float* __restrict__ g_w1)
{
    int c = blockIdx.x, tid = threadIdx.x;
    __shared__ float ces[64];
    if (tid < 64) ces[tid] = d_ce_g[c * 64 + tid];
    __syncthreads();
    float a = 0.f;
#pragma unroll 8
    for (int e = 0; e < 64; e++)
        a += ces[e] * g_w1[(1 + e) * 256 + tid];
    d_A_g[c * 256 + tid] = a;
}

// ------ k_B: B[g,h] = ge.w1[65:129] + shift*w1[129] + 128*w1[130] + b1 --
__global__ void k_B(const int* __restrict__ gidx, const float* __restrict__ shift_vec,
                    const float* __restrict__ gene_table, const float* __restrict__ g_w1,
                    const float* __restrict__ g_b1)
{
    int g = blockIdx.x, tid = threadIdx.x;
    __shared__ float ges[64];
    __shared__ float shs;
    int gs = gidx[g];
    if (tid < 64) ges[tid] = gene_table[gs * 64 + tid];
    if (tid == 0) shs = shift_vec[gs];
    __syncthreads();
    float a = g_b1[tid] + 128.0f * g_w1[130 * 256 + tid] + shs * g_w1[129 * 256 + tid];
#pragma unroll 8
    for (int e = 0; e < 64; e++)
        a += ges[e] * g_w1[(65 + e) * 256 + tid];
    d_B_g[g * 256 + tid] = a;
}

// ======================= k3: fully fused per-gene ========================
// Per gene g:
//   x[c,h]   = elu(ctrl[c,g]*w1row0[h] + A[c,h] + B[g,h])      (generated per 64-h chunk)
//   p[h]     = mean_c x[c,h]                                    (accumulated during gen)
//   GEMM:      acc = x @ W2a  via mma.sync tf32 (m16n8k8)
//   q[n]     = p @ W2b + b2
//   x2       = acc + q   (never materialized to gmem)
//   p2[h]    = mean_c x2[c,h]   (column sums of acc tiles)
//   cgene    = sum_h w3b[h]*elu(p2[h]) + b3
//   x3[c]    = sum_h w3a[h]*elu(x2[c,h]) + cgene   (row sums of acc tiles)
//   out[:,g] = softmax_c(x3)
//
// smem layout (floats):
#define SM_CTRL   0          // 128
#define SM_RS     128        // 256  (w1 row 0)
#define SM_BS     384        // 256
#define SM_QS     640        // 256
#define SM_PSUM   896        // 256
#define SM_PPART  1152       // 512  (also reused: softmax scratch)
#define SM_QPART  1664       // 512
#define SM_W3A    2176       // 256
#define SM_W3B    2432       // 256
#define SM_X3     2688       // 128
#define SM_XS     2816       // 128 rows * 68 = 8704  (A tiles, tf32 bits)
#define SM_WS     11520      // 64 rows * 264 = 16896 (B tiles, tf32 bits)
#define K3_SMEM_FLOATS (SM_WS + 16896)
// colred/rowred/cred alias into ws region after GEMM:
#define SM_COLRED SM_WS          // 4*256
#define SM_ROWRED (SM_WS + 1024) // 4*128
#define SM_CRED   (SM_WS + 1536) // 256

__global__ __launch_bounds__(512, 1) void k3(
    const float* __restrict__ ctrl, const int* __restrict__ gidx,
    const float* __restrict__ g_w1, const float* __restrict__ g_w2,
    const float* __restrict__ g_b2, const float* __restrict__ g_w3,
    const float* __restrict__ g_b3, float* __restrict__ out)
{
    extern __shared__ float sm[];
    unsigned* usm = (unsigned*)sm;

    int g = blockIdx.x, tid = threadIdx.x;
    int lane = tid & 31, w = tid >> 5;
    int lg = lane >> 2, lt = lane & 3;        // mma group / thread-in-group
    int wr = w >> 2, wc = w & 3;              // warp tile coords (4x4)
    int gs = gidx[g];

    // prologue loads
    for (int i = tid; i < 128; i += 512) sm[SM_CTRL + i] = ctrl[i * Gg + gs];
    for (int i = tid; i < 256; i += 512) {
        sm[SM_RS + i]  = g_w1[i];
        sm[SM_BS + i]  = d_B_g[g * 256 + i];
        sm[SM_W3A + i] = g_w3[i];
        sm[SM_W3B + i] = g_w3[256 + i];
    }

    float acc[2][8][4];
#pragma unroll
    for (int i = 0; i < 2; i++)
#pragma unroll
        for (int j = 0; j < 8; j++)
#pragma unroll
            for (int k = 0; k < 4; k++) acc[i][j][k] = 0.f;

    // -------- 4 chunks of 64 k --------
    for (int kc = 0; kc < 4; kc++) {
        __syncthreads();
        // load W2a chunk rows [kc*64, kc*64+64) as tf32 bits, padded stride 264
        for (int i = tid; i < 16384; i += 512) {
            int r = i >> 8, n = i & 255;
            usm[SM_WS + r * 264 + n] = f2tf32(g_w2[(kc * 64 + r) * 256 + n]);
        }
        // generate x chunk (rows c, cols k local), accumulate p partial
        {
            int hl = tid & 63;
            int h = kc * 64 + hl;
            float rv = sm[SM_RS + h];
            float Bv = sm[SM_BS + h];
            float lps = 0.f;
#pragma unroll 4
            for (int k = 0; k < 16; k++) {
                int c = (tid >> 6) + 8 * k;
                float v = eluf(sm[SM_CTRL + c] * rv + d_A_g[c * 256 + h] + Bv);
                usm[SM_XS + c * 68 + hl] = f2tf32(v);
                lps += v;
            }
            sm[SM_PPART + hl * 8 + (tid >> 6)] = lps;
        }
        __syncthreads();
        if (tid < 64) {
            float s = 0.f;
#pragma unroll
            for (int j = 0; j < 8; j++) s += sm[SM_PPART + tid * 8 + j];
            sm[SM_PSUM + kc * 64 + tid] = s;
        }
        // mainloop: 8 k-steps of 8
#pragma unroll
        for (int ks = 0; ks < 8; ks++) {
            int k0 = ks * 8;
            unsigned a[2][4], b[8][2];
#pragma unroll
            for (int ra = 0; ra < 2; ra++) {
                int r0 = wr * 32 + ra * 16 + lg;
                a[ra][0] = usm[SM_XS + r0 * 68 + k0 + lt];
                a[ra][1] = usm[SM_XS + (r0 + 8) * 68 + k0 + lt];
                a[ra][2] = usm[SM_XS + r0 * 68 + k0 + lt + 4];
                a[ra][3] = usm[SM_XS + (r0 + 8) * 68 + k0 + lt + 4];
            }
#pragma unroll
            for (int cb = 0; cb < 8; cb++) {
                int n = wc * 64 + cb * 8 + lg;
                b[cb][0] = usm[SM_WS + (k0 + lt) * 264 + n];
                b[cb][1] = usm[SM_WS + (k0 + lt + 4) * 264 + n];
            }
#pragma unroll
            for (int ra = 0; ra < 2; ra++)
#pragma unroll
                for (int cb = 0; cb < 8; cb++)
                    mma_tf32(acc[ra][cb], a[ra], b[cb]);
        }
    }
    __syncthreads();

    // -------- q = p @ W2b + b2 (512 threads, split-h) --------
    {
        int n = tid & 255, half = tid >> 8;
        float qp = 0.f;
#pragma unroll 4
        for (int h = 0; h < 128; h++) {
            int hh = half * 128 + h;
            qp += (sm[SM_PSUM + hh] * (1.f / 128.f)) * g_w2[(256 + hh) * 256 + n];
        }
        sm[SM_QPART + tid] = qp;
    }
    __syncthreads();
    if (tid < 256)
        sm[SM_QS + tid] = sm[SM_QPART + tid] + sm[SM_QPART + 256 + tid] + g_b2[tid];
    __syncthreads();

    // -------- epilogue: row/col sums from acc tiles --------
    float rsum[4] = {0.f, 0.f, 0.f, 0.f};
    float csum[16];
#pragma unroll
    for (int i = 0; i < 16; i++) csum[i] = 0.f;
#pragma unroll
    for (int cb = 0; cb < 8; cb++) {
#pragma unroll
        for (int ra = 0; ra < 2; ra++) {
#pragma unroll
            for (int jj = 0; jj < 4; jj++) {
                int col = wc * 64 + cb * 8 + 2 * lt + (jj & 1);
                float v = acc[ra][cb][jj] + sm[SM_QS + col];
                csum[cb * 2 + (jj & 1)] += v;
                rsum[ra * 2 + (jj >> 1)] += sm[SM_W3A + col] * eluf(v);
            }
        }
    }
    // column reduce over lg (masks 4,8,16)
#pragma unroll
    for (int m = 4; m <= 16; m <<= 1)
#pragma unroll
        for (int i = 0; i < 16; i++) csum[i] += __shfl_xor_sync(0xffffffffu, csum[i], m);
    // row reduce over lt (masks 1,2)
#pragma unroll
    for (int m = 1; m <= 2; m <<= 1)
#pragma unroll
        for (int i = 0; i < 4; i++) rsum[i] += __shfl_xor_sync(0xffffffffu, rsum[i], m);
    if (lg == 0) {
#pragma unroll
        for (int cb = 0; cb < 8; cb++)
#pragma unroll
            for (int j = 0; j < 2; j++)
                sm[SM_COLRED + wr * 256 + wc * 64 + cb * 8 + 2 * lt + j] = csum[cb * 2 + j];
    }
    if (lt == 0) {
#pragma unroll
        for (int ri = 0; ri < 4; ri++)
            sm[SM_ROWRED + wc * 128 + wr * 32 + (ri >> 1) * 16 + (ri & 1) * 8 + lg] = rsum[ri];
    }
    __syncthreads();

    // cgene = sum_h w3b[h]*elu(p2[h]) + b3
    if (tid < 256) {
        float s = sm[SM_COLRED + tid] + sm[SM_COLRED + 256 + tid] +
                  sm[SM_COLRED + 512 + tid] + sm[SM_COLRED + 768 + tid];
        float p2 = s * (1.f / 128.f);
        sm[SM_CRED + tid] = sm[SM_W3B + tid] * eluf(p2);
    }
    __syncthreads();
    for (int off = 128; off > 0; off >>= 1) {
        if (tid < off) sm[SM_CRED + tid] += sm[SM_CRED + tid + off];
        __syncthreads();
    }
    float cgene = sm[SM_CRED] + g_b3[0];

    // x3[c] and softmax over 128 cells
    if (tid < 128)
        sm[SM_X3 + tid] = sm[SM_ROWRED + tid] + sm[SM_ROWRED + 128 + tid] +
                          sm[SM_ROWRED + 256 + tid] + sm[SM_ROWRED + 384 + tid] + cgene;
    __syncthreads();
    if (tid < 128) sm[SM_PPART + tid] = sm[SM_X3 + tid];
    __syncthreads();
    for (int off = 64; off > 0; off >>= 1) {
        if (tid < off) sm[SM_PPART + tid] = fmaxf(sm[SM_PPART + tid], sm[SM_PPART + tid + off]);
        __syncthreads();
    }
    float mx = sm[SM_PPART];
    __syncthreads();
    float ev = 0.f;
    if (tid < 128) {
        ev = __expf(sm[SM_X3 + tid] - mx);
        sm[SM_PPART + tid] = ev;
    }
    __syncthreads();
    for (int off = 64; off > 0; off >>= 1) {
        if (tid < off) sm[SM_PPART + tid] += sm[SM_PPART + tid + off];
        __syncthreads();
    }
    if (tid < 128) out[tid * Gg + g] = ev / sm[SM_PPART];
}

// -------------------------------------------------------------------------
extern "C" void kernel_launch(void* const* d_in, const int* in_sizes, int n_in,
                              void* d_out, int out_size)
{
    const float* ctrl       = (const float*)d_in[0];
    const float* shift_vec  = (const float*)d_in[1];
    const int*   gidx       = (const int*)d_in[2];
    const float* ce_w1      = (const float*)d_in[3];
    const float* ce_b1      = (const float*)d_in[4];
    const float* ce_w2      = (const float*)d_in[5];
    const float* ce_b2      = (const float*)d_in[6];
    const float* gene_table = (const float*)d_in[7];
    const float* g_w1       = (const float*)d_in[8];
    const float* g_b1       = (const float*)d_in[9];
    const float* g_w2       = (const float*)d_in[10];
    const float* g_b2       = (const float*)d_in[11];
    const float* g_w3       = (const float*)d_in[12];
    const float* g_b3       = (const float*)d_in[13];
    float* out = (float*)d_out;

    cudaFuncSetAttribute(k3, cudaFuncAttributeMaxDynamicSharedMemorySize,
                         K3_SMEM_FLOATS * (int)sizeof(float));

    k_ce<<<Cc, 1024>>>(ctrl, ce_w1, ce_b1, ce_w2, ce_b2);
    k_A<<<Cc, 256>>>(g_w1);
    k_B<<<Gg, 256>>>(gidx, shift_vec, gene_table, g_w1, g_b1);
    k3<<<Gg, 512, K3_SMEM_FLOATS * sizeof(float)>>>(ctrl, gidx, g_w1, g_w2,
                                                    g_b2, g_w3, g_b3, out);
}

// round 3
// speedup vs baseline: 3.7948x; 1.1972x over previous
#include <cuda_runtime.h>
#include <cuda_bf16.h>
#include <cstdint>

#define Cc 128
#define Gg 2000
#define Hh 256

// ---------------- scratch (device globals; no allocation) ----------------
__device__ float d_ce_g[Cc * 64];             // [128,64]
__device__ float d_A_g[Cc * Hh];              // [128,256]
__device__ float d_B_g[Gg * Hh];              // [2000,256]

__device__ __forceinline__ float eluf(float x) {
    return x > 0.f ? x : (__expf(x) - 1.f);
}

__device__ __forceinline__ void mma_tf32(float* acc, const unsigned* a, const unsigned* b) {
    asm volatile(
        "mma.sync.aligned.m16n8k8.row.col.f32.tf32.tf32.f32 "
        "{%0,%1,%2,%3}, {%4,%5,%6,%7}, {%8,%9}, {%0,%1,%2,%3};"
        : "+f"(acc[0]), "+f"(acc[1]), "+f"(acc[2]), "+f"(acc[3])
        : "r"(a[0]), "r"(a[1]), "r"(a[2]), "r"(a[3]), "r"(b[0]), "r"(b[1]));
}

__device__ __forceinline__ uint32_t smem_u32(const void* p) {
    uint32_t a;
    asm("{ .reg .u64 t; cvta.to.shared.u64 t, %1; cvt.u32.u64 %0, t; }" : "=r"(a) : "l"(p));
    return a;
}
__device__ __forceinline__ void cpasync16(uint32_t dst, const void* src) {
    asm volatile("cp.async.ca.shared.global [%0], [%1], 16;" :: "r"(dst), "l"(src));
}
__device__ __forceinline__ void cp_commit() { asm volatile("cp.async.commit_group;"); }
template <int N> __device__ __forceinline__ void cp_wait() {
    asm volatile("cp.async.wait_group %0;" :: "n"(N));
}

// ---------------- k_ce: ce = elu(ctrl@ce_w1+b1)@ce_w2+b2  [128,64] ------
__global__ __launch_bounds__(1024) void k_ce(
    const float* __restrict__ ctrl, const float* __restrict__ ce_w1,
    const float* __restrict__ ce_b1, const float* __restrict__ ce_w2,
    const float* __restrict__ ce_b2)
{
    int c = blockIdx.x, tid = threadIdx.x;
    __shared__ float row[Gg];
    __shared__ float part[4][256];
    __shared__ float h1[256];
    for (int i = tid; i < Gg; i += 1024) row[i] = ctrl[c * Gg + i];
    __syncthreads();
    int sl = tid >> 8, t = tid & 255;
    float acc = 0.f;
    for (int k = sl * 500; k < sl * 500 + 500; k++)
        acc += row[k] * ce_w1[k * 256 + t];
    part[sl][t] = acc;
    __syncthreads();
    if (tid < 256) {
        float v = part[0][tid] + part[1][tid] + part[2][tid] + part[3][tid] + ce_b1[tid];
        h1[tid] = eluf(v);
    }
    __syncthreads();
    if (tid < 256) {
        int s2 = tid >> 6, e = tid & 63;
        float a2 = 0.f;
        for (int h = s2 * 64; h < s2 * 64 + 64; h++)
            a2 += h1[h] * ce_w2[h * 64 + e];
        part[s2][e] = a2;
    }
    __syncthreads();
    if (tid < 64)
        d_ce_g[c * 64 + tid] = part[0][tid] + part[1][tid] + part[2][tid] + part[3][tid] + ce_b2[tid];
}

// ---------------- k_A: A[c,h] = ce[c,:] . w1[1:65,h] --------------------
__global__ void k_A(const float* __restrict__ g_w1)
{
    int c = blockIdx.x, tid = threadIdx.x;
    __shared__ float ces[64];
    if (tid < 64) ces[tid] = d_ce_g[c * 64 + tid];
    __syncthreads();
    float a = 0.f;
#pragma unroll 8
    for (int e = 0; e < 64; e++)
        a += ces[e] * g_w1[(1 + e) * 256 + tid];
    d_A_g[c * 256 + tid] = a;
}

// ------ k_B: B[g,h] = ge.w1[65:129] + shift*w1[129] + 128*w1[130] + b1 --
__global__ void k_B(const int* __restrict__ gidx, const float* __restrict__ shift_vec,
                    const float* __restrict__ gene_table, const float* __restrict__ g_w1,
                    const float* __restrict__ g_b1)
{
    int g = blockIdx.x, tid = threadIdx.x;
    __shared__ float ges[64];
    __shared__ float shs;
    int gs = gidx[g];
    if (tid < 64) ges[tid] = gene_table[gs * 64 + tid];
    if (tid == 0) shs = shift_vec[gs];
    __syncthreads();
    float a = g_b1[tid] + 128.0f * g_w1[130 * 256 + tid] + shs * g_w1[129 * 256 + tid];
#pragma unroll 8
    for (int e = 0; e < 64; e++)
        a += ges[e] * g_w1[(65 + e) * 256 + tid];
    d_B_g[g * 256 + tid] = a;
}

// ======================= k3: fully fused per-gene ========================
// Pipelined: cp.async double-buffered W2a chunks; double-buffered x tiles.
// smem layout (floats):
#define SM_CTRL   0          // 128
#define SM_RS     128        // 256
#define SM_BS     384        // 256
#define SM_QS     640        // 256
#define SM_PSUM   896        // 256
#define SM_PPA    1152       // 512  (p partials, even chunks; softmax scratch)
#define SM_PPB    1664       // 512  (p partials, odd chunks)
#define SM_QPART  2176       // 512
#define SM_W3A    2688       // 256
#define SM_W3B    2944       // 256
#define SM_X3     3200       // 128
#define SM_XS0    3328       // 128*68 = 8704
#define SM_XS1    12032      // 8704
#define SM_WS0    20736      // 64*264 = 16896
#define SM_WS1    37632      // 16896
#define K3_SMEM_FLOATS 54528 // 218112 bytes
// epilogue aliases (into WS0, free after last MMA chunk reads WS1):
#define SM_COLRED SM_WS0            // 4*256
#define SM_ROWRED (SM_WS0 + 1024)   // 4*128
#define SM_CRED   (SM_WS0 + 1536)   // 256

__global__ __launch_bounds__(512, 1) void k3(
    const float* __restrict__ ctrl, const int* __restrict__ gidx,
    const float* __restrict__ g_w1, const float* __restrict__ g_w2,
    const float* __restrict__ g_b2, const float* __restrict__ g_w3,
    const float* __restrict__ g_b3, float* __restrict__ out)
{
    extern __shared__ float sm[];
    unsigned* usm = (unsigned*)sm;
    uint32_t sbase = smem_u32(sm);

    int g = blockIdx.x, tid = threadIdx.x;
    int lane = tid & 31, w = tid >> 5;
    int lg = lane >> 2, lt = lane & 3;
    int wr = w >> 2, wc = w & 3;
    int gs = gidx[g];

    // ---- prologue: misc loads + first two W chunks in flight ----
    for (int i = tid; i < 128; i += 512) sm[SM_CTRL + i] = ctrl[i * Gg + gs];
    for (int i = tid; i < 256; i += 512) {
        sm[SM_RS + i]  = g_w1[i];
        sm[SM_BS + i]  = d_B_g[g * 256 + i];
        sm[SM_W3A + i] = g_w3[i];
        sm[SM_W3B + i] = g_w3[256 + i];
    }

    // cp.async W chunk kc into buffer at float-offset wofs
#define CPW(kc, wofs)                                                        \
    {                                                                        \
        const float* src_ = g_w2 + (kc) * 64 * 256;                          \
        for (int i = tid; i < 4096; i += 512) {                              \
            int r_ = i >> 6, cp_ = i & 63;                                   \
            cpasync16(sbase + ((wofs) + r_ * 264 + cp_ * 4) * 4,             \
                      src_ + r_ * 256 + cp_ * 4);                            \
        }                                                                    \
        cp_commit();                                                         \
    }

    // generate x chunk kc into buffer xofs, p-partials into pofs
#define GENX(kc, xofs, pofs)                                                 \
    {                                                                        \
        int hl_ = tid & 63;                                                  \
        int h_ = (kc) * 64 + hl_;                                            \
        float rv_ = sm[SM_RS + h_];                                          \
        float Bv_ = sm[SM_BS + h_];                                          \
        float lps_ = 0.f;                                                    \
        _Pragma("unroll 4")                                                  \
        for (int k_ = 0; k_ < 16; k_++) {                                    \
            int c_ = (tid >> 6) + 8 * k_;                                    \
            float v_ = eluf(sm[SM_CTRL + c_] * rv_ + d_A_g[c_ * 256 + h_] + Bv_); \
            usm[(xofs) + c_ * 68 + hl_] = __float_as_uint(v_);               \
            lps_ += v_;                                                      \
        }                                                                    \
        sm[(pofs) + hl_ * 8 + (tid >> 6)] = lps_;                            \
    }

#define REDP(kc, pofs)                                                       \
    if (tid < 64) {                                                          \
        float s_ = 0.f;                                                      \
        _Pragma("unroll")                                                    \
        for (int j_ = 0; j_ < 8; j_++) s_ += sm[(pofs) + tid * 8 + j_];      \
        sm[SM_PSUM + (kc) * 64 + tid] = s_;                                  \
    }

    CPW(0, SM_WS0);
    CPW(1, SM_WS1);
    GENX(0, SM_XS0, SM_PPA);
    cp_wait<1>();        // W0 arrived (locally)
    __syncthreads();     // x0, W0, misc visible
    REDP(0, SM_PPA);

    float acc[2][8][4];
#pragma unroll
    for (int i = 0; i < 2; i++)
#pragma unroll
        for (int j = 0; j < 8; j++)
#pragma unroll
            for (int k = 0; k < 4; k++) acc[i][j][k] = 0.f;

#pragma unroll
    for (int it = 0; it < 4; it++) {
        int xb = (it & 1) ? SM_XS1 : SM_XS0;
        int wb = (it & 1) ? SM_WS1 : SM_WS0;
        // ---- MMA on chunk it ----
#pragma unroll
        for (int ks = 0; ks < 8; ks++) {
            int k0 = ks * 8;
            unsigned a[2][4], b[8][2];
#pragma unroll
            for (int ra = 0; ra < 2; ra++) {
                int r0 = wr * 32 + ra * 16 + lg;
                a[ra][0] = usm[xb + r0 * 68 + k0 + lt];
                a[ra][1] = usm[xb + (r0 + 8) * 68 + k0 + lt];
                a[ra][2] = usm[xb + r0 * 68 + k0 + lt + 4];
                a[ra][3] = usm[xb + (r0 + 8) * 68 + k0 + lt + 4];
            }
#pragma unroll
            for (int cb = 0; cb < 8; cb++) {
                int n = wc * 64 + cb * 8 + lg;
                b[cb][0] = usm[wb + (k0 + lt) * 264 + n];
                b[cb][1] = usm[wb + (k0 + lt + 4) * 264 + n];
            }
#pragma unroll
            for (int ra = 0; ra < 2; ra++)
#pragma unroll
                for (int cb = 0; cb < 8; cb++)
                    mma_tf32(acc[ra][cb], a[ra], b[cb]);
        }
        // ---- generate next x chunk (overlaps other warps' MMA) ----
        if (it == 0) GENX(1, SM_XS1, SM_PPB);
        if (it == 1) GENX(2, SM_XS0, SM_PPA);
        if (it == 2) GENX(3, SM_XS1, SM_PPB);
        __syncthreads();   // all MMA(it) + genx(it+1) complete
        if (it == 0) REDP(1, SM_PPB);
        if (it == 1) REDP(2, SM_PPA);
        if (it == 2) REDP(3, SM_PPB);
        // ---- refill W buffer just freed; ensure next W arrived ----
        if (it == 0) { CPW(2, SM_WS0); cp_wait<1>(); }
        if (it == 1) { CPW(3, SM_WS1); cp_wait<1>(); }
        if (it == 2) { cp_wait<0>(); }
        if (it < 3) __syncthreads();
    }
    __syncthreads();

    // -------- q = p @ W2b + b2 --------
    {
        int n = tid & 255, half = tid >> 8;
        float qp = 0.f;
#pragma unroll 4
        for (int h = 0; h < 128; h++) {
            int hh = half * 128 + h;
            qp += (sm[SM_PSUM + hh] * (1.f / 128.f)) * g_w2[(256 + hh) * 256 + n];
        }
        sm[SM_QPART + tid] = qp;
    }
    __syncthreads();
    if (tid < 256)
        sm[SM_QS + tid] = sm[SM_QPART + tid] + sm[SM_QPART + 256 + tid] + g_b2[tid];
    __syncthreads();

    // -------- epilogue: row/col sums from acc tiles --------
    float rsum[4] = {0.f, 0.f, 0.f, 0.f};
    float csum[16];
#pragma unroll
    for (int i = 0; i < 16; i++) csum[i] = 0.f;
#pragma unroll
    for (int cb = 0; cb < 8; cb++) {
#pragma unroll
        for (int ra = 0; ra < 2; ra++) {
#pragma unroll
            for (int jj = 0; jj < 4; jj++) {
                int col = wc * 64 + cb * 8 + 2 * lt + (jj & 1);
                float v = acc[ra][cb][jj] + sm[SM_QS + col];
                csum[cb * 2 + (jj & 1)] += v;
                rsum[ra * 2 + (jj >> 1)] += sm[SM_W3A + col] * eluf(v);
            }
        }
    }
#pragma unroll
    for (int m = 4; m <= 16; m <<= 1)
#pragma unroll
        for (int i = 0; i < 16; i++) csum[i] += __shfl_xor_sync(0xffffffffu, csum[i], m);
#pragma unroll
    for (int m = 1; m <= 2; m <<= 1)
#pragma unroll
        for (int i = 0; i < 4; i++) rsum[i] += __shfl_xor_sync(0xffffffffu, rsum[i], m);
    if (lg == 0) {
#pragma unroll
        for (int cb = 0; cb < 8; cb++)
#pragma unroll
            for (int j = 0; j < 2; j++)
                sm[SM_COLRED + wr * 256 + wc * 64 + cb * 8 + 2 * lt + j] = csum[cb * 2 + j];
    }
    if (lt == 0) {
#pragma unroll
        for (int ri = 0; ri < 4; ri++)
            sm[SM_ROWRED + wc * 128 + wr * 32 + (ri >> 1) * 16 + (ri & 1) * 8 + lg] = rsum[ri];
    }
    __syncthreads();

    if (tid < 256) {
        float s = sm[SM_COLRED + tid] + sm[SM_COLRED + 256 + tid] +
                  sm[SM_COLRED + 512 + tid] + sm[SM_COLRED + 768 + tid];
        float p2 = s * (1.f / 128.f);
        sm[SM_CRED + tid] = sm[SM_W3B + tid] * eluf(p2);
    }
    __syncthreads();
    for (int off = 128; off > 0; off >>= 1) {
        if (tid < off) sm[SM_CRED + tid] += sm[SM_CRED + tid + off];
        __syncthreads();
    }
    float cgene = sm[SM_CRED] + g_b3[0];

    if (tid < 128)
        sm[SM_X3 + tid] = sm[SM_ROWRED + tid] + sm[SM_ROWRED + 128 + tid] +
                          sm[SM_ROWRED + 256 + tid] + sm[SM_ROWRED + 384 + tid] + cgene;
    __syncthreads();
    if (tid < 128) sm[SM_PPA + tid] = sm[SM_X3 + tid];
    __syncthreads();
    for (int off = 64; off > 0; off >>= 1) {
        if (tid < off) sm[SM_PPA + tid] = fmaxf(sm[SM_PPA + tid], sm[SM_PPA + tid + off]);
        __syncthreads();
    }
    float mx = sm[SM_PPA];
    __syncthreads();
    float ev = 0.f;
    if (tid < 128) {
        ev = __expf(sm[SM_X3 + tid] - mx);
        sm[SM_PPA + tid] = ev;
    }
    __syncthreads();
    for (int off = 64; off > 0; off >>= 1) {
        if (tid < off) sm[SM_PPA + tid] += sm[SM_PPA + tid + off];
        __syncthreads();
    }
    if (tid < 128) out[tid * Gg + g] = ev / sm[SM_PPA];
}

// -------------------------------------------------------------------------
extern "C" void kernel_launch(void* const* d_in, const int* in_sizes, int n_in,
                              void* d_out, int out_size)
{
    const float* ctrl       = (const float*)d_in[0];
    const float* shift_vec  = (const float*)d_in[1];
    const int*   gidx       = (const int*)d_in[2];
    const float* ce_w1      = (const float*)d_in[3];
    const float* ce_b1      = (const float*)d_in[4];
    const float* ce_w2      = (const float*)d_in[5];
    const float* ce_b2      = (const float*)d_in[6];
    const float* gene_table = (const float*)d_in[7];
    const float* g_w1       = (const float*)d_in[8];
    const float* g_b1       = (const float*)d_in[9];
    const float* g_w2       = (const float*)d_in[10];
    const float* g_b2       = (const float*)d_in[11];
    const float* g_w3       = (const float*)d_in[12];
    const float* g_b3       = (const float*)d_in[13];
    float* out = (float*)d_out;

    cudaFuncSetAttribute(k3, cudaFuncAttributeMaxDynamicSharedMemorySize,
                         K3_SMEM_FLOATS * (int)sizeof(float));

    k_ce<<<Cc, 1024>>>(ctrl, ce_w1, ce_b1, ce_w2, ce_b2);
    k_A<<<Cc, 256>>>(g_w1);
    k_B<<<Gg, 256>>>(gidx, shift_vec, gene_table, g_w1, g_b1);
    k3<<<Gg, 512, K3_SMEM_FLOATS * sizeof(float)>>>(ctrl, gidx, g_w1, g_w2,
                                                    g_b2, g_w3, g_b3, out);
}